// round 14
// baseline (speedup 1.0000x reference)
#include <cuda_runtime.h>

#define NB   32
#define CC   512
#define LL   512
#define KG   10
#define VK   8
#define LT   32          // l-tile per block
#define NT   (LL/LT)     // 16 tiles per n

typedef unsigned long long u64;

// Scratch (no allocations allowed)
__device__ float g_asum[NB * NT * VK];        // per-tile assign_sum partials
__device__ float g_axp [NB * NT * VK * CC];   // per-tile assign_x partials (8 MB)
__device__ int   g_ctr [NB];                  // arrival counters (zero-init, self-resetting)

__device__ __forceinline__ u64 pack2(float lo, float hi) {
    u64 r; asm("mov.b64 %0,{%1,%2};" : "=l"(r) : "f"(lo), "f"(hi)); return r;
}
__device__ __forceinline__ void unpack2(u64 v, float& lo, float& hi) {
    asm("mov.b64 {%0,%1},%2;" : "=f"(lo), "=f"(hi) : "l"(v));
}
__device__ __forceinline__ u64 ffma2(u64 a, u64 b, u64 c) {
    u64 d; asm("fma.rn.f32x2 %0,%1,%2,%3;" : "=l"(d) : "l"(a), "l"(b), "l"(c)); return d;
}

// Dynamic smem layout (floats): xs[32][513] | psh[8][10][32] | as8[4][32] u64
#define XS_F   (LT * 513)            // 16416 floats (x tile, 513-pad: conflict-free)
#define PSH_F  (8 * KG * LT)         // 2560 floats (per-warp partial logits)
#define DYN_BYTES ((XS_F + PSH_F) * 4 + 4 * LT * 8)   // 75904 + 1024 = 76928 B

// ---------------------------------------------------------------------------
// Fused kernel: logits + softmax + assign_x partials, x read ONCE.
// grid (NT, NB), block 256, 2 CTAs/SM. Last block per n runs the epilogue.
// ---------------------------------------------------------------------------
__global__ __launch_bounds__(256, 2) void fused_ghostvlad(
    const float* __restrict__ x, const float* __restrict__ w,
    const float* __restrict__ b, const float* __restrict__ centers,
    float* __restrict__ out)
{
    extern __shared__ __align__(16) float dyn[];
    float* xs  = dyn;                       // xs[l*513 + c]
    float* psh = dyn + XS_F;                // psh[warp*320 + k*32 + l]
    u64*   as8 = (u64*)(dyn + XS_F + PSH_F);// as8[kp*32 + l]

    __shared__ float wsh[CC * 12];          // [c][k] 12-padded
    __shared__ float asum_sh[VK];
    __shared__ float red2[8][VK];
    __shared__ float scale_sh[VK];
    __shared__ int   is_last;

    const int tid  = threadIdx.x;
    const int lane = tid & 31;
    const int warp = tid >> 5;
    const int n    = blockIdx.y;
    const int tile = blockIdx.x;
    const int l0g  = tile * LT;             // global l base of this tile

    for (int i = tid; i < KG * CC; i += 256) {
        int k = i >> 9, c = i & (CC - 1);
        wsh[c * 12 + k] = w[i];
    }
    __syncthreads();

    // ---- Phase 1: logits (lane = l, warp owns 64 c), stage x into xs ----
    {
        const int c0 = warp * 64;
        u64 acc[5];
#pragma unroll
        for (int p = 0; p < 5; p++) acc[p] = 0ull;

        const float* xp = x + ((size_t)n * CC + c0) * LL + l0g + lane;
#pragma unroll 1
        for (int cb = 0; cb < 64; cb += 16) {
            float xv[16];
#pragma unroll
            for (int i = 0; i < 16; i++) xv[i] = xp[(cb + i) * LL];   // 16 LDG in flight
#pragma unroll
            for (int i = 0; i < 16; i++)
                xs[lane * 513 + c0 + cb + i] = xv[i];                 // conflict-free STS
#pragma unroll
            for (int i = 0; i < 16; i++) {
                u64 xd = pack2(xv[i], xv[i]);
                const float* wr = wsh + (c0 + cb + i) * 12;
                acc[0] = ffma2(*(const u64*)(wr + 0), xd, acc[0]);
                acc[1] = ffma2(*(const u64*)(wr + 2), xd, acc[1]);
                acc[2] = ffma2(*(const u64*)(wr + 4), xd, acc[2]);
                acc[3] = ffma2(*(const u64*)(wr + 6), xd, acc[3]);
                acc[4] = ffma2(*(const u64*)(wr + 8), xd, acc[4]);
            }
        }

        float lg[KG];
#pragma unroll
        for (int p = 0; p < 5; p++) unpack2(acc[p], lg[2 * p], lg[2 * p + 1]);
#pragma unroll
        for (int k = 0; k < KG; k++)
            psh[warp * (KG * LT) + k * LT + lane] = lg[k];
    }
    __syncthreads();

    // ---- Phase 2: warp 0 combines + softmax + a (smem only) + asum ----
    if (tid < 32) {
        float lg[KG];
#pragma unroll
        for (int k = 0; k < KG; k++) lg[k] = __ldg(b + k);
#pragma unroll
        for (int wp = 0; wp < 8; wp++)
#pragma unroll
            for (int k = 0; k < KG; k++)
                lg[k] += psh[wp * (KG * LT) + k * LT + lane];

        float m = lg[0];
#pragma unroll
        for (int k = 1; k < KG; k++) m = fmaxf(m, lg[k]);
        float s = 0.f;
#pragma unroll
        for (int k = 0; k < KG; k++) { lg[k] = __expf(lg[k] - m); s += lg[k]; }
        float inv = 1.f / s;
#pragma unroll
        for (int k = 0; k < VK; k++) lg[k] *= inv;

        // a to smem k-pair planes: as8[kp][l]
#pragma unroll
        for (int kp = 0; kp < 4; kp++)
            as8[kp * LT + lane] = pack2(lg[2 * kp], lg[2 * kp + 1]);

        // octet reduce-scatter over lg[0..7], fold 32 lanes -> asum partial
#pragma unroll
        for (int o = 4; o >= 1; o >>= 1) {
            bool up = (lane & o) != 0;
#pragma unroll
            for (int i = 0; i < 8; i++) {
                if (i < o) {
                    float keep = up ? lg[i + o] : lg[i];
                    float send = up ? lg[i] : lg[i + o];
                    lg[i] = keep + __shfl_xor_sync(0xffffffffu, send, o);
                }
            }
        }
        float t0 = lg[0];
        t0 += __shfl_xor_sync(0xffffffffu, t0, 8);
        t0 += __shfl_xor_sync(0xffffffffu, t0, 16);
        if (lane < 8) g_asum[((size_t)n * NT + tile) * VK + lane] = t0;
    }
    __syncthreads();

    // ---- Phase 3: assign partials. Thread owns cA=tid, cB=tid+256. ----
    {
        const int cA = tid, cB = tid + 256;
        u64 acc[2][4];
#pragma unroll
        for (int ci = 0; ci < 2; ci++)
#pragma unroll
            for (int kp = 0; kp < 4; kp++) acc[ci][kp] = 0ull;

#pragma unroll 4
        for (int l = 0; l < LT; l++) {
            u64 a0 = as8[0 * LT + l], a1 = as8[1 * LT + l];
            u64 a2 = as8[2 * LT + l], a3 = as8[3 * LT + l];
            float xA = xs[l * 513 + cA];
            float xB = xs[l * 513 + cB];
            u64 xdA = pack2(xA, xA), xdB = pack2(xB, xB);
            acc[0][0] = ffma2(a0, xdA, acc[0][0]);
            acc[0][1] = ffma2(a1, xdA, acc[0][1]);
            acc[0][2] = ffma2(a2, xdA, acc[0][2]);
            acc[0][3] = ffma2(a3, xdA, acc[0][3]);
            acc[1][0] = ffma2(a0, xdB, acc[1][0]);
            acc[1][1] = ffma2(a1, xdB, acc[1][1]);
            acc[1][2] = ffma2(a2, xdB, acc[1][2]);
            acc[1][3] = ffma2(a3, xdB, acc[1][3]);
        }

        // Each (k,c) owned by exactly one thread -> no reduction, direct STG.
        float* pbase = g_axp + (((size_t)n * NT + tile) * VK) * CC;
#pragma unroll
        for (int kp = 0; kp < 4; kp++) {
            float vA0, vA1, vB0, vB1;
            unpack2(acc[0][kp], vA0, vA1);
            unpack2(acc[1][kp], vB0, vB1);
            pbase[(2 * kp)     * CC + cA] = vA0;
            pbase[(2 * kp + 1) * CC + cA] = vA1;
            pbase[(2 * kp)     * CC + cB] = vB0;
            pbase[(2 * kp + 1) * CC + cB] = vB1;
        }
    }

    // ---- arrival: 16th block for this n runs the epilogue ----
    __syncthreads();
    if (tid == 0) {
        __threadfence();
        int old = atomicAdd(&g_ctr[n], 1);
        is_last = (old == NT - 1);
    }
    __syncthreads();
    if (!is_last) return;
    __threadfence();

    if (tid < VK) {
        float s = 0.f;
#pragma unroll
        for (int t = 0; t < NT; t++)
            s += g_asum[((size_t)n * NT + t) * VK + tid];
        asum_sh[tid] = s;
    }
    __syncthreads();

    // sum 16 tile-partials, residual vs centers; stage residuals in xs
    float sq[VK];
    {
        const float* pbase = g_axp + ((size_t)n * NT) * VK * CC;
#pragma unroll
        for (int k = 0; k < VK; k++) {
            float sA = 0.f, sB = 0.f;
#pragma unroll
            for (int t = 0; t < NT; t++) {
                const float* pr = pbase + ((size_t)t * VK + k) * CC;
                sA += pr[tid];
                sB += pr[tid + 256];
            }
            const float* cr = centers + k * CC;
            float rA = sA - asum_sh[k] * cr[tid];
            float rB = sB - asum_sh[k] * cr[tid + 256];
            xs[k * CC + tid]       = rA;
            xs[k * CC + tid + 256] = rB;
            sq[k] = rA * rA + rB * rB;
        }
    }

    // octet reduce-scatter within warp, then cross-warp via smem
#pragma unroll
    for (int o = 4; o >= 1; o >>= 1) {
        bool up = (lane & o) != 0;
#pragma unroll
        for (int i = 0; i < 8; i++) {
            if (i < o) {
                float keep = up ? sq[i + o] : sq[i];
                float send = up ? sq[i] : sq[i + o];
                sq[i] = keep + __shfl_xor_sync(0xffffffffu, send, o);
            }
        }
    }
    {
        float t0 = sq[0];
        t0 += __shfl_xor_sync(0xffffffffu, t0, 8);
        t0 += __shfl_xor_sync(0xffffffffu, t0, 16);
        if (lane < 8) red2[warp][lane] = t0;
    }
    __syncthreads();

    if (warp == 0) {
        int k = lane & 7;
        float ss = 0.f;
#pragma unroll
        for (int wp = 0; wp < 8; wp++) ss += red2[wp][k];
        float s1 = 1.f / fmaxf(sqrtf(ss), 1e-12f);
        float vlad = ss * s1 * s1;
        vlad += __shfl_xor_sync(0xffffffffu, vlad, 4);
        vlad += __shfl_xor_sync(0xffffffffu, vlad, 2);
        vlad += __shfl_xor_sync(0xffffffffu, vlad, 1);
        float fs = 1.f / fmaxf(sqrtf(vlad), 1e-12f);
        if (lane < 8) scale_sh[k] = s1 * fs;
    }
    __syncthreads();

#pragma unroll
    for (int k = 0; k < VK; k++) {
        float* o = out + (size_t)n * VK * CC + k * CC;
        o[tid]       = xs[k * CC + tid]       * scale_sh[k];
        o[tid + 256] = xs[k * CC + tid + 256] * scale_sh[k];
    }

    if (tid == 0) g_ctr[n] = 0;   // re-arm for next replay
}

// ---------------------------------------------------------------------------
extern "C" void kernel_launch(void* const* d_in, const int* in_sizes, int n_in,
                              void* d_out, int out_size)
{
    const float* x       = (const float*)d_in[0];  // [32,512,16,32]
    const float* conv_w  = (const float*)d_in[1];  // [10,512]
    const float* conv_b  = (const float*)d_in[2];  // [10]
    const float* centers = (const float*)d_in[3];  // [10,512]
    float* out = (float*)d_out;                    // [32, 4096]

    cudaFuncSetAttribute(fused_ghostvlad,
                         cudaFuncAttributeMaxDynamicSharedMemorySize, DYN_BYTES);

    fused_ghostvlad<<<dim3(NT, NB), 256, DYN_BYTES>>>(x, conv_w, conv_b, centers, out);
}

// round 15
// speedup vs baseline: 1.2749x; 1.2749x over previous
#include <cuda_runtime.h>

#define NB   32
#define CC   512
#define LL   512
#define KG   10
#define VK   8

typedef unsigned long long u64;

// Scratch (no allocations allowed)
__device__ u64   g_a   [NB * 4 * LL];         // assignments as k-pair planes [n][kp][l]
__device__ float g_asum[NB * 8 * VK];         // per-l-tile assign_sum partials
__device__ float g_axp [NB * VK * CC];        // assign_x [n][k][c]
__device__ int   g_ctr [NB];                  // arrival counters (zero-init, self-resetting)

__device__ __forceinline__ u64 pack2(float lo, float hi) {
    u64 r; asm("mov.b64 %0,{%1,%2};" : "=l"(r) : "f"(lo), "f"(hi)); return r;
}
__device__ __forceinline__ void unpack2(u64 v, float& lo, float& hi) {
    asm("mov.b64 {%0,%1},%2;" : "=f"(lo), "=f"(hi) : "l"(v));
}
__device__ __forceinline__ u64 ffma2(u64 a, u64 b, u64 c) {
    u64 d; asm("fma.rn.f32x2 %0,%1,%2,%3;" : "=l"(d) : "l"(a), "l"(b), "l"(c)); return d;
}

// ---------------------------------------------------------------------------
// KA: logits + softmax + a + assign_sum partials, fused. (unchanged, proven)
// grid (L/64, N), block 256.
// ---------------------------------------------------------------------------
__global__ __launch_bounds__(256) void ka_logits_softmax(
    const float* __restrict__ x, const float* __restrict__ w,
    const float* __restrict__ b)
{
    __shared__ float wsh[CC * 12];        // 24 KB, [c][k] 12-padded
    __shared__ float psh[8 * KG * 64];    // 20 KB, [warp][k][l_local]
    __shared__ float red[2][VK];

    const int tid   = threadIdx.x;
    const int lane  = tid & 31;
    const int warp  = tid >> 5;
    const int n     = blockIdx.y;
    const int lbase = blockIdx.x * 64;

    for (int i = tid; i < KG * CC; i += 256) {
        int k = i >> 9, c = i & (CC - 1);
        wsh[c * 12 + k] = w[i];
    }
    __syncthreads();

    u64 accA[5], accB[5];
#pragma unroll
    for (int p = 0; p < 5; p++) { accA[p] = 0ull; accB[p] = 0ull; }

    const int c0 = warp * 64;
    const float* xp = x + ((size_t)n * CC + c0) * LL + lbase + lane * 2;
#pragma unroll 1
    for (int cb = 0; cb < 64; cb += 16) {
        const float* xc = xp + (size_t)cb * LL;
        float2 xv[16];
#pragma unroll
        for (int i = 0; i < 16; i++) xv[i] = *(const float2*)(xc + i * LL);
#pragma unroll
        for (int i = 0; i < 16; i++) {
            u64 xa = pack2(xv[i].x, xv[i].x);
            u64 xb = pack2(xv[i].y, xv[i].y);
            const float* wr = wsh + (c0 + cb + i) * 12;
            u64 w0 = *(const u64*)(wr + 0);
            u64 w1 = *(const u64*)(wr + 2);
            u64 w2 = *(const u64*)(wr + 4);
            u64 w3 = *(const u64*)(wr + 6);
            u64 w4 = *(const u64*)(wr + 8);
            accA[0] = ffma2(w0, xa, accA[0]);  accB[0] = ffma2(w0, xb, accB[0]);
            accA[1] = ffma2(w1, xa, accA[1]);  accB[1] = ffma2(w1, xb, accB[1]);
            accA[2] = ffma2(w2, xa, accA[2]);  accB[2] = ffma2(w2, xb, accB[2]);
            accA[3] = ffma2(w3, xa, accA[3]);  accB[3] = ffma2(w3, xb, accB[3]);
            accA[4] = ffma2(w4, xa, accA[4]);  accB[4] = ffma2(w4, xb, accB[4]);
        }
    }

    {
        float lgA[KG], lgB[KG];
#pragma unroll
        for (int p = 0; p < 5; p++) {
            unpack2(accA[p], lgA[2 * p], lgA[2 * p + 1]);
            unpack2(accB[p], lgB[2 * p], lgB[2 * p + 1]);
        }
        float* pr = psh + (warp * KG) * 64 + lane * 2;
#pragma unroll
        for (int k = 0; k < KG; k++) {
            float2 v; v.x = lgA[k]; v.y = lgB[k];
            *(float2*)(pr + k * 64) = v;
        }
    }
    __syncthreads();

    if (tid < 64) {
        float lg[KG];
#pragma unroll
        for (int k = 0; k < KG; k++) lg[k] = __ldg(b + k);
#pragma unroll
        for (int wp = 0; wp < 8; wp++) {
            const float* pr = psh + (wp * KG) * 64 + tid;
#pragma unroll
            for (int k = 0; k < KG; k++) lg[k] += pr[k * 64];
        }

        float m = lg[0];
#pragma unroll
        for (int k = 1; k < KG; k++) m = fmaxf(m, lg[k]);
        float s = 0.f;
#pragma unroll
        for (int k = 0; k < KG; k++) { lg[k] = __expf(lg[k] - m); s += lg[k]; }
        float inv = 1.f / s;

#pragma unroll
        for (int k = 0; k < VK; k++) lg[k] *= inv;

        // a as k-pair planes [n][kp][l]: 4 coalesced STG.64
        u64* ap = g_a + (size_t)n * 4 * LL + lbase + tid;
#pragma unroll
        for (int kp = 0; kp < 4; kp++)
            ap[kp * LL] = pack2(lg[2 * kp], lg[2 * kp + 1]);

#pragma unroll
        for (int o = 4; o >= 1; o >>= 1) {
            bool up = (lane & o) != 0;
#pragma unroll
            for (int i = 0; i < 8; i++) {
                if (i < o) {
                    float keep = up ? lg[i + o] : lg[i];
                    float send = up ? lg[i] : lg[i + o];
                    lg[i] = keep + __shfl_xor_sync(0xffffffffu, send, o);
                }
            }
        }
        float t0 = lg[0];
        t0 += __shfl_xor_sync(0xffffffffu, t0, 8);
        t0 += __shfl_xor_sync(0xffffffffu, t0, 16);
        if (lane < 8) red[warp][lane] = t0;
    }
    __syncthreads();
    if (tid < VK)
        g_asum[((size_t)n * 8 + blockIdx.x) * VK + tid] = red[0][tid] + red[1][tid];
}

// ---------------------------------------------------------------------------
// KB: assign_x in KA's streaming mold. grid (C/16, N), block 256.
// Warp owns 2 c-rows over all 512 l; per c-row a 16-deep LDG.32 batch
// (the proven-batchable shape) streams the contiguous 2 KB row.
// smem = only the 16 KB a-planes -> 4 CTAs/SM; regs natural (~56-64).
// Last block per n runs the epilogue.
// ---------------------------------------------------------------------------
__global__ __launch_bounds__(256) void kb_assign_epilogue(
    const float* __restrict__ x, const float* __restrict__ centers,
    float* __restrict__ out)
{
    __shared__ __align__(16) u64 as8[4 * LL];   // 16 KB, a k-pair planes [kp][l]
    __shared__ float asum_sh[VK];
    __shared__ float red2[8][VK];
    __shared__ float scale_sh[VK];
    __shared__ int   is_last;

    const int tid  = threadIdx.x;
    const int lane = tid & 31;
    const int warp = tid >> 5;
    const int n    = blockIdx.y;
    const int c0   = blockIdx.x * 16 + warp * 2;

    {
        const u64* ag = g_a + (size_t)n * 4 * LL;
#pragma unroll
        for (int i = 0; i < 8; i++) as8[tid + i * 256] = ag[tid + i * 256];
    }
    __syncthreads();

    u64 acc[2][4];
#pragma unroll
    for (int ci = 0; ci < 2; ci++)
#pragma unroll
        for (int kp = 0; kp < 4; kp++) acc[ci][kp] = 0ull;

    const float* xb = x + ((size_t)n * CC + c0) * LL + lane;

#pragma unroll
    for (int ci = 0; ci < 2; ci++) {
        const float* xc = xb + ci * LL;
        float xv[16];
#pragma unroll
        for (int i = 0; i < 16; i++) xv[i] = xc[i * 32];   // 16 LDG.32 in flight
#pragma unroll
        for (int i = 0; i < 16; i++) {
            const int l = i * 32 + lane;
            u64 xd = pack2(xv[i], xv[i]);
            acc[ci][0] = ffma2(as8[0 * LL + l], xd, acc[ci][0]);
            acc[ci][1] = ffma2(as8[1 * LL + l], xd, acc[ci][1]);
            acc[ci][2] = ffma2(as8[2 * LL + l], xd, acc[ci][2]);
            acc[ci][3] = ffma2(as8[3 * LL + l], xd, acc[ci][3]);
        }
    }

    // 16 outputs/thread -> butterfly reduce-scatter (lane bits 3..0), fold 16.
    {
        float v[16];
#pragma unroll
        for (int ci = 0; ci < 2; ci++)
#pragma unroll
            for (int kp = 0; kp < 4; kp++)
                unpack2(acc[ci][kp], v[ci * 8 + 2 * kp], v[ci * 8 + 2 * kp + 1]);

#pragma unroll
        for (int o = 8; o >= 1; o >>= 1) {
            bool up = (lane & o) != 0;
#pragma unroll
            for (int i = 0; i < 16; i++) {
                if (i < o) {
                    float keep = up ? v[i + o] : v[i];
                    float send = up ? v[i] : v[i + o];
                    v[i] = keep + __shfl_xor_sync(0xffffffffu, send, o);
                }
            }
        }
        v[0] += __shfl_xor_sync(0xffffffffu, v[0], 16);

        if (lane < 16) {
            int ci = lane >> 3, k = lane & 7;
            g_axp[((size_t)n * VK + k) * CC + c0 + ci] = v[0];
        }
    }

    // ---- arrival: 32nd block for this n runs the epilogue ----
    __syncthreads();
    if (tid == 0) {
        __threadfence();
        int old = atomicAdd(&g_ctr[n], 1);
        is_last = (old == 31);
    }
    __syncthreads();
    if (!is_last) return;
    __threadfence();

    float* ashf = (float*)as8;   // 4096-float overlay for residual staging

    if (tid < VK) {
        float s = 0.f;
#pragma unroll
        for (int blk = 0; blk < 8; blk++)
            s += g_asum[((size_t)n * 8 + blk) * VK + tid];
        asum_sh[tid] = s;
    }
    __syncthreads();

    // residuals -> smem (reg-light cold path); thread owns c = tid, tid+256
    float sq[VK];
#pragma unroll
    for (int k = 0; k < VK; k++) {
        const float* axr = g_axp + ((size_t)n * VK + k) * CC;
        const float* cr  = centers + k * CC;
        float rA = axr[tid]       - asum_sh[k] * cr[tid];
        float rB = axr[tid + 256] - asum_sh[k] * cr[tid + 256];
        ashf[k * CC + tid]       = rA;
        ashf[k * CC + tid + 256] = rB;
        sq[k] = rA * rA + rB * rB;
    }

    // octet reduce-scatter within warp, then cross-warp via smem
#pragma unroll
    for (int o = 4; o >= 1; o >>= 1) {
        bool up = (lane & o) != 0;
#pragma unroll
        for (int i = 0; i < 8; i++) {
            if (i < o) {
                float keep = up ? sq[i + o] : sq[i];
                float send = up ? sq[i] : sq[i + o];
                sq[i] = keep + __shfl_xor_sync(0xffffffffu, send, o);
            }
        }
    }
    {
        float t0 = sq[0];
        t0 += __shfl_xor_sync(0xffffffffu, t0, 8);
        t0 += __shfl_xor_sync(0xffffffffu, t0, 16);
        if (lane < 8) red2[warp][lane] = t0;
    }
    __syncthreads();

    if (warp == 0) {
        int k = lane & 7;
        float ss = 0.f;
#pragma unroll
        for (int wp = 0; wp < 8; wp++) ss += red2[wp][k];
        float s1 = 1.f / fmaxf(sqrtf(ss), 1e-12f);
        float vlad = ss * s1 * s1;
        vlad += __shfl_xor_sync(0xffffffffu, vlad, 4);
        vlad += __shfl_xor_sync(0xffffffffu, vlad, 2);
        vlad += __shfl_xor_sync(0xffffffffu, vlad, 1);
        float fs = 1.f / fmaxf(sqrtf(vlad), 1e-12f);
        if (lane < 8) scale_sh[k] = s1 * fs;
    }
    __syncthreads();

#pragma unroll
    for (int k = 0; k < VK; k++) {
        float* o = out + (size_t)n * VK * CC + k * CC;
        o[tid]       = ashf[k * CC + tid]       * scale_sh[k];
        o[tid + 256] = ashf[k * CC + tid + 256] * scale_sh[k];
    }

    if (tid == 0) g_ctr[n] = 0;   // re-arm for next replay
}

// ---------------------------------------------------------------------------
extern "C" void kernel_launch(void* const* d_in, const int* in_sizes, int n_in,
                              void* d_out, int out_size)
{
    const float* x       = (const float*)d_in[0];  // [32,512,16,32]
    const float* conv_w  = (const float*)d_in[1];  // [10,512]
    const float* conv_b  = (const float*)d_in[2];  // [10]
    const float* centers = (const float*)d_in[3];  // [10,512]
    float* out = (float*)d_out;                    // [32, 4096]

    ka_logits_softmax <<<dim3(LL / 64, NB), 256>>>(x, conv_w, conv_b);
    kb_assign_epilogue<<<dim3(CC / 16, NB), 256>>>(x, centers, out);
}

// round 16
// speedup vs baseline: 1.5160x; 1.1892x over previous
#include <cuda_runtime.h>

#define NB   32
#define CC   512
#define LL   512
#define KG   10
#define VK   8

typedef unsigned long long u64;

// Scratch (no allocations allowed)
__device__ u64   g_a   [NB * 4 * LL];         // assignments as k-pair planes [n][kp][l]
__device__ float g_asum[NB * 8 * VK];         // per-l-tile assign_sum partials
__device__ float g_axp [NB * VK * CC];        // assign_x [n][k][c]
__device__ int   g_ctr [NB];                  // arrival counters (zero-init, self-resetting)

__device__ __forceinline__ u64 pack2(float lo, float hi) {
    u64 r; asm("mov.b64 %0,{%1,%2};" : "=l"(r) : "f"(lo), "f"(hi)); return r;
}
__device__ __forceinline__ void unpack2(u64 v, float& lo, float& hi) {
    asm("mov.b64 {%0,%1},%2;" : "=f"(lo), "=f"(hi) : "l"(v));
}
__device__ __forceinline__ u64 ffma2(u64 a, u64 b, u64 c) {
    u64 d; asm("fma.rn.f32x2 %0,%1,%2,%3;" : "=l"(d) : "l"(a), "l"(b), "l"(c)); return d;
}

// ---------------------------------------------------------------------------
// KA: logits + softmax + a + assign_sum partials, fused. (unchanged, proven)
// grid (L/64, N), block 256.
// ---------------------------------------------------------------------------
__global__ __launch_bounds__(256) void ka_logits_softmax(
    const float* __restrict__ x, const float* __restrict__ w,
    const float* __restrict__ b)
{
    __shared__ float wsh[CC * 12];        // 24 KB, [c][k] 12-padded
    __shared__ float psh[8 * KG * 64];    // 20 KB, [warp][k][l_local]
    __shared__ float red[2][VK];

    const int tid   = threadIdx.x;
    const int lane  = tid & 31;
    const int warp  = tid >> 5;
    const int n     = blockIdx.y;
    const int lbase = blockIdx.x * 64;

    for (int i = tid; i < KG * CC; i += 256) {
        int k = i >> 9, c = i & (CC - 1);
        wsh[c * 12 + k] = w[i];
    }
    __syncthreads();

    u64 accA[5], accB[5];
#pragma unroll
    for (int p = 0; p < 5; p++) { accA[p] = 0ull; accB[p] = 0ull; }

    const int c0 = warp * 64;
    const float* xp = x + ((size_t)n * CC + c0) * LL + lbase + lane * 2;
#pragma unroll 1
    for (int cb = 0; cb < 64; cb += 16) {
        const float* xc = xp + (size_t)cb * LL;
        float2 xv[16];
#pragma unroll
        for (int i = 0; i < 16; i++) xv[i] = *(const float2*)(xc + i * LL);
#pragma unroll
        for (int i = 0; i < 16; i++) {
            u64 xa = pack2(xv[i].x, xv[i].x);
            u64 xb = pack2(xv[i].y, xv[i].y);
            const float* wr = wsh + (c0 + cb + i) * 12;
            u64 w0 = *(const u64*)(wr + 0);
            u64 w1 = *(const u64*)(wr + 2);
            u64 w2 = *(const u64*)(wr + 4);
            u64 w3 = *(const u64*)(wr + 6);
            u64 w4 = *(const u64*)(wr + 8);
            accA[0] = ffma2(w0, xa, accA[0]);  accB[0] = ffma2(w0, xb, accB[0]);
            accA[1] = ffma2(w1, xa, accA[1]);  accB[1] = ffma2(w1, xb, accB[1]);
            accA[2] = ffma2(w2, xa, accA[2]);  accB[2] = ffma2(w2, xb, accB[2]);
            accA[3] = ffma2(w3, xa, accA[3]);  accB[3] = ffma2(w3, xb, accB[3]);
            accA[4] = ffma2(w4, xa, accA[4]);  accB[4] = ffma2(w4, xb, accB[4]);
        }
    }

    {
        float lgA[KG], lgB[KG];
#pragma unroll
        for (int p = 0; p < 5; p++) {
            unpack2(accA[p], lgA[2 * p], lgA[2 * p + 1]);
            unpack2(accB[p], lgB[2 * p], lgB[2 * p + 1]);
        }
        float* pr = psh + (warp * KG) * 64 + lane * 2;
#pragma unroll
        for (int k = 0; k < KG; k++) {
            float2 v; v.x = lgA[k]; v.y = lgB[k];
            *(float2*)(pr + k * 64) = v;
        }
    }
    __syncthreads();

    if (tid < 64) {
        float lg[KG];
#pragma unroll
        for (int k = 0; k < KG; k++) lg[k] = __ldg(b + k);
#pragma unroll
        for (int wp = 0; wp < 8; wp++) {
            const float* pr = psh + (wp * KG) * 64 + tid;
#pragma unroll
            for (int k = 0; k < KG; k++) lg[k] += pr[k * 64];
        }

        float m = lg[0];
#pragma unroll
        for (int k = 1; k < KG; k++) m = fmaxf(m, lg[k]);
        float s = 0.f;
#pragma unroll
        for (int k = 0; k < KG; k++) { lg[k] = __expf(lg[k] - m); s += lg[k]; }
        float inv = 1.f / s;

#pragma unroll
        for (int k = 0; k < VK; k++) lg[k] *= inv;

        // a as k-pair planes [n][kp][l]: 4 coalesced STG.64
        u64* ap = g_a + (size_t)n * 4 * LL + lbase + tid;
#pragma unroll
        for (int kp = 0; kp < 4; kp++)
            ap[kp * LL] = pack2(lg[2 * kp], lg[2 * kp + 1]);

#pragma unroll
        for (int o = 4; o >= 1; o >>= 1) {
            bool up = (lane & o) != 0;
#pragma unroll
            for (int i = 0; i < 8; i++) {
                if (i < o) {
                    float keep = up ? lg[i + o] : lg[i];
                    float send = up ? lg[i] : lg[i + o];
                    lg[i] = keep + __shfl_xor_sync(0xffffffffu, send, o);
                }
            }
        }
        float t0 = lg[0];
        t0 += __shfl_xor_sync(0xffffffffu, t0, 8);
        t0 += __shfl_xor_sync(0xffffffffu, t0, 16);
        if (lane < 8) red[warp][lane] = t0;
    }
    __syncthreads();
    if (tid < VK)
        g_asum[((size_t)n * 8 + blockIdx.x) * VK + tid] = red[0][tid] + red[1][tid];
}

// ---------------------------------------------------------------------------
// KB: assign_x with KA's exact load shape: per j-step the warp issues
// 8 LDG.64 to 8 DISTINCT 2KB-strided c-rows (8 L2-slice groups, depth 1)
// instead of streaming one contiguous row. Warp owns 8 c; acc[8][4]
// k-pair-packed u64. grid (C/64, N), block 256, 2 CTAs/SM (128-reg budget).
// Last block per n runs the epilogue.
// ---------------------------------------------------------------------------
__global__ __launch_bounds__(256, 2) void kb_assign_epilogue(
    const float* __restrict__ x, const float* __restrict__ centers,
    float* __restrict__ out)
{
    __shared__ __align__(16) u64 as8[4 * LL];   // 16 KB, a k-pair planes [kp][l]
    __shared__ float asum_sh[VK];
    __shared__ float red2[8][VK];
    __shared__ float scale_sh[VK];
    __shared__ int   is_last;

    const int tid   = threadIdx.x;
    const int lane  = tid & 31;
    const int warp  = tid >> 5;
    const int n     = blockIdx.y;
    const int cbase = blockIdx.x * 64 + warp * 8;

    {
        const u64* ag = g_a + (size_t)n * 4 * LL;
#pragma unroll
        for (int i = 0; i < 8; i++) as8[tid + i * 256] = ag[tid + i * 256];
    }
    __syncthreads();

    u64 acc[8][4];
#pragma unroll
    for (int r = 0; r < 8; r++)
#pragma unroll
        for (int kp = 0; kp < 4; kp++) acc[r][kp] = 0ull;

    const float* xb = x + ((size_t)n * CC + cbase) * LL + lane * 2;

#pragma unroll
    for (int j = 0; j < 8; j++) {
        const int l0 = j * 64;
        float2 xv[8];
#pragma unroll
        for (int r = 0; r < 8; r++)
            xv[r] = *(const float2*)(xb + r * LL + l0);   // 8 rows, 2KB apart

        const int la = l0 + lane * 2;
        u64 aA[4], aB[4];
#pragma unroll
        for (int kp = 0; kp < 4; kp++) {                  // LDS.128 pairs
            aA[kp] = as8[kp * LL + la];
            aB[kp] = as8[kp * LL + la + 1];
        }

#pragma unroll
        for (int r = 0; r < 8; r++) {
            u64 xlo = pack2(xv[r].x, xv[r].x);
            u64 xhi = pack2(xv[r].y, xv[r].y);
#pragma unroll
            for (int kp = 0; kp < 4; kp++) {
                acc[r][kp] = ffma2(aA[kp], xlo, acc[r][kp]);
                acc[r][kp] = ffma2(aB[kp], xhi, acc[r][kp]);
            }
        }
    }

    // Two 32-value butterfly reduce-scatters (proven): lane L keeps v[L].
#pragma unroll
    for (int g = 0; g < 2; g++) {
        float v[32];
#pragma unroll
        for (int ci = 0; ci < 4; ci++)
#pragma unroll
            for (int kp = 0; kp < 4; kp++)
                unpack2(acc[g * 4 + ci][kp], v[ci * 8 + 2 * kp], v[ci * 8 + 2 * kp + 1]);

#pragma unroll
        for (int o = 16; o >= 1; o >>= 1) {
            bool up = (lane & o) != 0;
#pragma unroll
            for (int i = 0; i < 32; i++) {
                if (i < o) {
                    float keep = up ? v[i + o] : v[i];
                    float send = up ? v[i] : v[i + o];
                    v[i] = keep + __shfl_xor_sync(0xffffffffu, send, o);
                }
            }
        }

        int ci = lane >> 3, k = lane & 7;
        g_axp[((size_t)n * VK + k) * CC + cbase + g * 4 + ci] = v[0];
    }

    // ---- arrival: 8th block for this n runs the epilogue ----
    __syncthreads();
    if (tid == 0) {
        __threadfence();
        int old = atomicAdd(&g_ctr[n], 1);
        is_last = (old == 7);
    }
    __syncthreads();
    if (!is_last) return;
    __threadfence();

    float* ashf = (float*)as8;   // 4096-float overlay for residual staging

    if (tid < VK) {
        float s = 0.f;
#pragma unroll
        for (int blk = 0; blk < 8; blk++)
            s += g_asum[((size_t)n * 8 + blk) * VK + tid];
        asum_sh[tid] = s;
    }
    __syncthreads();

    // residuals -> smem (reg-light cold path); thread owns c = tid, tid+256
    float sq[VK];
#pragma unroll
    for (int k = 0; k < VK; k++) {
        const float* axr = g_axp + ((size_t)n * VK + k) * CC;
        const float* cr  = centers + k * CC;
        float rA = axr[tid]       - asum_sh[k] * cr[tid];
        float rB = axr[tid + 256] - asum_sh[k] * cr[tid + 256];
        ashf[k * CC + tid]       = rA;
        ashf[k * CC + tid + 256] = rB;
        sq[k] = rA * rA + rB * rB;
    }

    // octet reduce-scatter within warp, then cross-warp via smem
#pragma unroll
    for (int o = 4; o >= 1; o >>= 1) {
        bool up = (lane & o) != 0;
#pragma unroll
        for (int i = 0; i < 8; i++) {
            if (i < o) {
                float keep = up ? sq[i + o] : sq[i];
                float send = up ? sq[i] : sq[i + o];
                sq[i] = keep + __shfl_xor_sync(0xffffffffu, send, o);
            }
        }
    }
    {
        float t0 = sq[0];
        t0 += __shfl_xor_sync(0xffffffffu, t0, 8);
        t0 += __shfl_xor_sync(0xffffffffu, t0, 16);
        if (lane < 8) red2[warp][lane] = t0;
    }
    __syncthreads();

    if (warp == 0) {
        int k = lane & 7;
        float ss = 0.f;
#pragma unroll
        for (int wp = 0; wp < 8; wp++) ss += red2[wp][k];
        float s1 = 1.f / fmaxf(sqrtf(ss), 1e-12f);
        float vlad = ss * s1 * s1;
        vlad += __shfl_xor_sync(0xffffffffu, vlad, 4);
        vlad += __shfl_xor_sync(0xffffffffu, vlad, 2);
        vlad += __shfl_xor_sync(0xffffffffu, vlad, 1);
        float fs = 1.f / fmaxf(sqrtf(vlad), 1e-12f);
        if (lane < 8) scale_sh[k] = s1 * fs;
    }
    __syncthreads();

#pragma unroll
    for (int k = 0; k < VK; k++) {
        float* o = out + (size_t)n * VK * CC + k * CC;
        o[tid]       = ashf[k * CC + tid]       * scale_sh[k];
        o[tid + 256] = ashf[k * CC + tid + 256] * scale_sh[k];
    }

    if (tid == 0) g_ctr[n] = 0;   // re-arm for next replay
}

// ---------------------------------------------------------------------------
extern "C" void kernel_launch(void* const* d_in, const int* in_sizes, int n_in,
                              void* d_out, int out_size)
{
    const float* x       = (const float*)d_in[0];  // [32,512,16,32]
    const float* conv_w  = (const float*)d_in[1];  // [10,512]
    const float* conv_b  = (const float*)d_in[2];  // [10]
    const float* centers = (const float*)d_in[3];  // [10,512]
    float* out = (float*)d_out;                    // [32, 4096]

    ka_logits_softmax <<<dim3(LL / 64, NB), 256>>>(x, conv_w, conv_b);
    kb_assign_epilogue<<<dim3(CC / 64, NB), 256>>>(x, centers, out);
}